// round 6
// baseline (speedup 1.0000x reference)
#include <cuda_runtime.h>
#include <cuda_bf16.h>
#include <cstdint>

#define MAXN 100000
#define MAXE 1600000
#define FI   64
#define H    4
#define D    16
#define ED   5
#define NEG_SLOPE 0.2f
#define SCAN_B 1024
#define MAXNB ((MAXN + SCAN_B - 1) / SCAN_B)   // 98
#define NPB   32                                // nodes per block in k_nodeproj

// ---------------- static device scratch --------------------------------------
__device__ float  g_featp[MAXN * FI];     // [N,64] projected feats (h*16+d)
__device__ float4 g_el[MAXN];             // [N,4]
__device__ float4 g_er[MAXN];             // [N,4]
__device__ float4 g_p4[MAXE];             // [E,4] unnormalized softmax weights
__device__ int    g_cnt[MAXN];            // degree histogram (by dst)
__device__ int    g_off[MAXN];            // CSR offsets
__device__ int    g_cur[MAXN];            // mutable cursor for bucketing
__device__ int    g_bsum[MAXNB];          // scan partials
__device__ int    g_boff[MAXNB];
__device__ int    g_eid[MAXE];            // edge ids sorted by dst
__device__ float  g_ft[MAXN * FI];        // [N,64] unnormalized feat aggregate
__device__ float  g_zs[MAXN * H * 8];     // [N,4,8] = {z, s0..s4, pad, pad}

// ---------------- kernel 1: zero degree counters ------------------------------
__global__ void k_zero(int N) {
    int t = blockIdx.x * blockDim.x + threadIdx.x;
    if (t < N) g_cnt[t] = 0;
}

// ---------------- kernel 2: node projection + el/er ---------------------------
// 32 nodes/block: W_fc (16KB) loaded into smem ONCE per block (8x less L2
// weight traffic than 4 nodes/block).
__global__ void k_nodeproj(const float* __restrict__ feat,
                           const float* __restrict__ W_fc,
                           const float* __restrict__ attn_l,
                           const float* __restrict__ attn_r, int N) {
    __shared__ float sW[FI * 64];
    __shared__ float sf[4][FI];
    int tid = threadIdx.x;
    #pragma unroll
    for (int i = tid; i < FI * 64; i += 256) sW[i] = W_fc[i];
    int nl = tid >> 6, j = tid & 63;
    int h = j >> 4, d = j & 15;
    float al = __ldg(&attn_l[h * D + d]);
    float ar = __ldg(&attn_r[h * D + d]);

    #pragma unroll
    for (int it = 0; it < NPB / 4; it++) {
        int n = blockIdx.x * NPB + it * 4 + nl;
        __syncthreads();                       // sW ready (it=0) / sf reuse safe
        if (n < N) sf[nl][j] = feat[n * FI + j];
        __syncthreads();
        if (n >= N) continue;

        float acc = 0.0f;
        #pragma unroll
        for (int i = 0; i < FI; i++) acc += sf[nl][i] * sW[i * 64 + j];
        g_featp[n * 64 + j] = acc;

        float elp = acc * al;
        float erp = acc * ar;
        #pragma unroll
        for (int off = 8; off; off >>= 1) {
            elp += __shfl_xor_sync(0xffffffffu, elp, off);
            erp += __shfl_xor_sync(0xffffffffu, erp, off);
        }
        if (d == 0) {
            ((float*)g_el)[n * 4 + h] = elp;
            ((float*)g_er)[n * 4 + h] = erp;
        }
    }
}

// ---------------- kernel 3: per-edge p (all 4 heads) + dst histogram ----------
// Folded logit: ee_h = ef . w_h + c_h with w_h = W_edg[:,h,:] @ attn_edg[h].
__global__ void k_passB(const float* __restrict__ edge_fea,
                        const int* __restrict__ src,
                        const int* __restrict__ dst,
                        const float* __restrict__ W_edg,
                        const float* __restrict__ b_edg,
                        const float* __restrict__ attn_edg, int E) {
    __shared__ float sw[H][ED];
    __shared__ float sc[H];
    int tid = threadIdx.x;
    if (tid < H * ED) {
        int h = tid / ED, j = tid % ED;
        float a = 0.0f;
        #pragma unroll
        for (int k = 0; k < ED; k++)
            a += W_edg[j * (H * ED) + h * ED + k] * attn_edg[h * ED + k];
        sw[h][j] = a;
    }
    if (tid < H) {
        float a = 0.0f;
        #pragma unroll
        for (int k = 0; k < ED; k++) a += b_edg[tid * ED + k] * attn_edg[tid * ED + k];
        sc[tid] = a;
    }
    __syncthreads();

    int e = blockIdx.x * blockDim.x + tid;
    if (e >= E) return;
    int s = __ldg(&src[e]), d = __ldg(&dst[e]);
    atomicAdd(&g_cnt[d], 1);

    float ef[ED];
    #pragma unroll
    for (int j = 0; j < ED; j++) ef[j] = __ldg(&edge_fea[e * ED + j]);

    float4 el = g_el[s], er = g_er[d];
    float p[H];
    #pragma unroll
    for (int h = 0; h < H; h++) {
        float ee = sc[h];
        #pragma unroll
        for (int j = 0; j < ED; j++) ee += ef[j] * sw[h][j];
        float elh = h == 0 ? el.x : h == 1 ? el.y : h == 2 ? el.z : el.w;
        float erh = h == 0 ? er.x : h == 1 ? er.y : h == 2 ? er.z : er.w;
        float x = elh + erh + ee;
        x = x > 0.0f ? x : NEG_SLOPE * x;
        p[h] = __expf(x);
    }
    g_p4[e] = make_float4(p[0], p[1], p[2], p[3]);
}

// ---------------- scan kernels (exclusive prefix sum over g_cnt) --------------
__global__ void k_scan1(int N) {
    __shared__ int sh[SCAN_B];
    int t = threadIdx.x;
    int g = blockIdx.x * SCAN_B + t;
    int v = (g < N) ? g_cnt[g] : 0;
    sh[t] = v;
    __syncthreads();
    #pragma unroll
    for (int off = 1; off < SCAN_B; off <<= 1) {
        int x = (t >= off) ? sh[t - off] : 0;
        __syncthreads();
        sh[t] += x;
        __syncthreads();
    }
    if (g < N) g_off[g] = sh[t] - v;            // exclusive
    if (t == SCAN_B - 1) g_bsum[blockIdx.x] = sh[t];
}
__global__ void k_scan2(int NB) {
    __shared__ int sh[128];
    int t = threadIdx.x;
    int v = (t < NB) ? g_bsum[t] : 0;
    sh[t] = v;
    __syncthreads();
    #pragma unroll
    for (int off = 1; off < 128; off <<= 1) {
        int x = (t >= off) ? sh[t - off] : 0;
        __syncthreads();
        sh[t] += x;
        __syncthreads();
    }
    if (t < NB) g_boff[t] = sh[t] - v;
}
__global__ void k_scan3(int N) {
    int g = blockIdx.x * blockDim.x + threadIdx.x;
    if (g < N) {
        int o = g_off[g] + g_boff[g / SCAN_B];
        g_off[g] = o;
        g_cur[g] = o;
    }
}

// ---------------- kernel: bucket edge ids by dst ------------------------------
__global__ void k_scatteridx(const int* __restrict__ dst, int E) {
    int e = blockIdx.x * blockDim.x + threadIdx.x;
    if (e >= E) return;
    int d = __ldg(&dst[e]);
    int pos = atomicAdd(&g_cur[d], 1);
    g_eid[pos] = e;
}

// ---------------- kernel: CSR aggregation, one warp per dst node --------------
// Batch-loads 32 (eid, src) pairs coalesced, broadcasts via shfl, so the inner
// loop's featp/p4 loads are mutually independent (high MLP). No atomics.
// Lane owns ft channels {lane, lane+32}; lanes 0..23 own one z/s slot.
__global__ void __launch_bounds__(256, 6)
k_passC(const float* __restrict__ edge_fea,
        const int* __restrict__ src, int N) {
    int warp = (blockIdx.x * blockDim.x + threadIdx.x) >> 5;
    int lane = threadIdx.x & 31;
    if (warp >= N) return;
    int off = g_off[warp];
    int deg = g_cnt[warp];

    int h2 = lane / 6, c = lane % 6;          // z/s mapping (lane<24)
    bool zs = lane < 24;
    int psel = lane >> 4;                      // selects head within pair

    float a0 = 0.0f, a1 = 0.0f, a2 = 0.0f;
    for (int base = 0; base < deg; base += 32) {
        int rem = deg - base;
        int cnt = rem < 32 ? rem : 32;
        // coalesced batch load of edge ids + src ids (one per lane)
        int myeid = (lane < cnt) ? __ldg(&g_eid[off + base + lane]) : 0;
        int mysrc = (lane < cnt) ? __ldg(&src[myeid]) : 0;
        #pragma unroll 4
        for (int i = 0; i < cnt; i++) {
            int eid = __shfl_sync(0xffffffffu, myeid, i);
            int s   = __shfl_sync(0xffffffffu, mysrc, i);
            float4 p4 = g_p4[eid];
            float pf0 = psel ? p4.y : p4.x;    // heads 0/1, channels 0..31
            float pf1 = psel ? p4.w : p4.z;    // heads 2/3, channels 32..63
            float v0 = __ldg(&g_featp[s * 64 + lane]);
            float v1 = __ldg(&g_featp[s * 64 + 32 + lane]);
            a0 += pf0 * v0;
            a1 += pf1 * v1;
            if (zs) {
                float ph = h2 == 0 ? p4.x : h2 == 1 ? p4.y : h2 == 2 ? p4.z : p4.w;
                float w = (c == 0) ? 1.0f : __ldg(&edge_fea[eid * ED + (c - 1)]);
                a2 += ph * w;
            }
        }
    }
    g_ft[warp * 64 + lane]      = a0;
    g_ft[warp * 64 + 32 + lane] = a1;
    if (zs) g_zs[(warp * H + h2) * 8 + c] = a2;
}

// ---------------- kernel: normalize + W_edg fold + output GEMV ----------------
__global__ void k_output(const float* __restrict__ W_edg,
                         const float* __restrict__ b_edg,
                         const float* __restrict__ W_out,
                         const float* __restrict__ b_out,
                         const float* __restrict__ bias,
                         float* __restrict__ out, int N) {
    __shared__ float sWo[(ED + D) * D];
    __shared__ float sWe[ED * H * ED];
    __shared__ float sbe[H * ED];
    __shared__ float sb[D];
    __shared__ float sbias[H * D];
    int tid = threadIdx.x;
    for (int i = tid; i < (ED + D) * D; i += 256) sWo[i] = W_out[i];
    if (tid < 100) sWe[tid] = W_edg[tid];
    if (tid < 20)  sbe[tid] = b_edg[tid];
    if (tid < D)   sb[tid] = b_out[tid];
    if (tid < H * D) sbias[tid] = bias[tid];
    __syncthreads();

    int nh = blockIdx.x * blockDim.x + tid;
    if (nh >= N * H) return;
    int n = nh >> 2, h = nh & 3;

    const float4* z4 = (const float4*)&g_zs[nh * 8];
    float4 a0 = z4[0], a1 = z4[1];
    float z = a0.x;
    float inv = z > 0.0f ? 1.0f / z : 0.0f;
    float s0 = a0.y, s1 = a0.z, s2 = a0.w, s3 = a1.x, s4 = a1.y;

    const float4* f4 = (const float4*)&g_ft[n * 64 + h * D];
    float4 b0 = f4[0], b1 = f4[1], b2 = f4[2], b3 = f4[3];
    float ft[D] = {b0.x, b0.y, b0.z, b0.w, b1.x, b1.y, b1.z, b1.w,
                   b2.x, b2.y, b2.z, b2.w, b3.x, b3.y, b3.z, b3.w};

    float ep[ED];
    #pragma unroll
    for (int k = 0; k < ED; k++) {
        float v = z * sbe[h * ED + k];
        v += s0 * sWe[0 * (H * ED) + h * ED + k];
        v += s1 * sWe[1 * (H * ED) + h * ED + k];
        v += s2 * sWe[2 * (H * ED) + h * ED + k];
        v += s3 * sWe[3 * (H * ED) + h * ED + k];
        v += s4 * sWe[4 * (H * ED) + h * ED + k];
        ep[k] = v * inv;
    }
    #pragma unroll
    for (int k = 0; k < D; k++) ft[k] *= inv;

    float o[D];
    #pragma unroll
    for (int dd = 0; dd < D; dd++) o[dd] = sb[dd] + sbias[h * D + dd];
    #pragma unroll
    for (int k = 0; k < ED; k++)
        #pragma unroll
        for (int dd = 0; dd < D; dd++) o[dd] += ep[k] * sWo[k * D + dd];
    #pragma unroll
    for (int k = 0; k < D; k++)
        #pragma unroll
        for (int dd = 0; dd < D; dd++) o[dd] += ft[k] * sWo[(ED + k) * D + dd];

    float4* op = (float4*)&out[nh * D];
    op[0] = make_float4(o[0],  o[1],  o[2],  o[3]);
    op[1] = make_float4(o[4],  o[5],  o[6],  o[7]);
    op[2] = make_float4(o[8],  o[9],  o[10], o[11]);
    op[3] = make_float4(o[12], o[13], o[14], o[15]);
}

// ---------------- launch ------------------------------------------------------
extern "C" void kernel_launch(void* const* d_in, const int* in_sizes, int n_in,
                              void* d_out, int out_size) {
    const float* feat     = (const float*)d_in[0];
    const float* edge_fea = (const float*)d_in[1];
    const int*   src      = (const int*)  d_in[2];
    const int*   dst      = (const int*)  d_in[3];
    const float* W_fc     = (const float*)d_in[4];
    const float* W_edg    = (const float*)d_in[5];
    const float* b_edg    = (const float*)d_in[6];
    const float* attn_l   = (const float*)d_in[7];
    const float* attn_r   = (const float*)d_in[8];
    const float* attn_edg = (const float*)d_in[9];
    const float* W_out    = (const float*)d_in[10];
    const float* b_out    = (const float*)d_in[11];
    const float* bias     = (const float*)d_in[12];
    float* out = (float*)d_out;

    int N = in_sizes[0] / FI;
    int E = in_sizes[2];
    if (N > MAXN) N = MAXN;
    if (E > MAXE) E = MAXE;
    int NB = (N + SCAN_B - 1) / SCAN_B;

    k_zero<<<(N + 255) / 256, 256>>>(N);
    k_nodeproj<<<(N + NPB - 1) / NPB, 256>>>(feat, W_fc, attn_l, attn_r, N);
    k_passB<<<(E + 255) / 256, 256>>>(edge_fea, src, dst, W_edg, b_edg, attn_edg, E);
    k_scan1<<<NB, SCAN_B>>>(N);
    k_scan2<<<1, 128>>>(NB);
    k_scan3<<<(N + 255) / 256, 256>>>(N);
    k_scatteridx<<<(E + 255) / 256, 256>>>(dst, E);
    k_passC<<<(N * 32 + 255) / 256, 256>>>(edge_fea, src, N);
    k_output<<<(N * H + 255) / 256, 256>>>(W_edg, b_edg, W_out, b_out, bias, out, N);
}

// round 8
// speedup vs baseline: 1.1759x; 1.1759x over previous
#include <cuda_runtime.h>
#include <cuda_bf16.h>
#include <cstdint>

#define MAXN 100000
#define MAXE 1600000
#define FI   64
#define H    4
#define D    16
#define ED   5
#define NEG_SLOPE 0.2f
#define SCAN_B 1024
#define MAXNB ((MAXN + SCAN_B - 1) / SCAN_B)   // 98
#define NPB   32                                // nodes per block in k_nodeproj

// ---------------- static device scratch --------------------------------------
__device__ float  g_featp[MAXN * FI];     // [N,64] projected feats (h*16+d)
__device__ float4 g_el[MAXN];             // [N,4]
__device__ float4 g_er[MAXN];             // [N,4]
__device__ float4 g_p4[MAXE];             // [E,4] unnormalized softmax weights
__device__ int    g_cnt[MAXN];            // degree histogram (by dst)
__device__ int    g_off[MAXN];            // CSR offsets
__device__ int    g_cur[MAXN];            // mutable cursor for bucketing
__device__ int    g_bsum[MAXNB];          // scan partials
__device__ int    g_boff[MAXNB];
__device__ int2   g_es[MAXE];             // {edge id, src} sorted by dst
__device__ float  g_ft[MAXN * FI];        // [N,64] unnormalized feat aggregate
__device__ float  g_zs[MAXN * H * 8];     // [N,4,8] = {z, s0..s4, pad, pad}

// ---------------- kernel 1: zero degree counters ------------------------------
__global__ void k_zero(int N) {
    int t = blockIdx.x * blockDim.x + threadIdx.x;
    if (t < N) g_cnt[t] = 0;
}

// ---------------- kernel 2: node projection + el/er ---------------------------
// 32 nodes/block: W_fc (16KB) loaded into smem ONCE per block.
__global__ void k_nodeproj(const float* __restrict__ feat,
                           const float* __restrict__ W_fc,
                           const float* __restrict__ attn_l,
                           const float* __restrict__ attn_r, int N) {
    __shared__ float sW[FI * 64];
    __shared__ float sf[4][FI];
    int tid = threadIdx.x;
    #pragma unroll
    for (int i = tid; i < FI * 64; i += 256) sW[i] = W_fc[i];
    int nl = tid >> 6, j = tid & 63;
    int h = j >> 4, d = j & 15;
    float al = __ldg(&attn_l[h * D + d]);
    float ar = __ldg(&attn_r[h * D + d]);

    #pragma unroll
    for (int it = 0; it < NPB / 4; it++) {
        int n = blockIdx.x * NPB + it * 4 + nl;
        __syncthreads();                       // sW ready (it=0) / sf reuse safe
        if (n < N) sf[nl][j] = feat[n * FI + j];
        __syncthreads();
        if (n >= N) continue;

        float acc = 0.0f;
        #pragma unroll
        for (int i = 0; i < FI; i++) acc += sf[nl][i] * sW[i * 64 + j];
        g_featp[n * 64 + j] = acc;

        float elp = acc * al;
        float erp = acc * ar;
        #pragma unroll
        for (int off = 8; off; off >>= 1) {
            elp += __shfl_xor_sync(0xffffffffu, elp, off);
            erp += __shfl_xor_sync(0xffffffffu, erp, off);
        }
        if (d == 0) {
            ((float*)g_el)[n * 4 + h] = elp;
            ((float*)g_er)[n * 4 + h] = erp;
        }
    }
}

// ---------------- kernel 3: per-edge p (all 4 heads) + dst histogram ----------
// Folded logit: ee_h = ef . w_h + c_h with w_h = W_edg[:,h,:] @ attn_edg[h].
__global__ void k_passB(const float* __restrict__ edge_fea,
                        const int* __restrict__ src,
                        const int* __restrict__ dst,
                        const float* __restrict__ W_edg,
                        const float* __restrict__ b_edg,
                        const float* __restrict__ attn_edg, int E) {
    __shared__ float sw[H][ED];
    __shared__ float sc[H];
    int tid = threadIdx.x;
    if (tid < H * ED) {
        int h = tid / ED, j = tid % ED;
        float a = 0.0f;
        #pragma unroll
        for (int k = 0; k < ED; k++)
            a += W_edg[j * (H * ED) + h * ED + k] * attn_edg[h * ED + k];
        sw[h][j] = a;
    }
    if (tid < H) {
        float a = 0.0f;
        #pragma unroll
        for (int k = 0; k < ED; k++) a += b_edg[tid * ED + k] * attn_edg[tid * ED + k];
        sc[tid] = a;
    }
    __syncthreads();

    int e = blockIdx.x * blockDim.x + tid;
    if (e >= E) return;
    int s = __ldg(&src[e]), d = __ldg(&dst[e]);
    atomicAdd(&g_cnt[d], 1);

    float ef[ED];
    #pragma unroll
    for (int j = 0; j < ED; j++) ef[j] = __ldg(&edge_fea[e * ED + j]);

    float4 el = g_el[s], er = g_er[d];
    float p[H];
    #pragma unroll
    for (int h = 0; h < H; h++) {
        float ee = sc[h];
        #pragma unroll
        for (int j = 0; j < ED; j++) ee += ef[j] * sw[h][j];
        float elh = h == 0 ? el.x : h == 1 ? el.y : h == 2 ? el.z : el.w;
        float erh = h == 0 ? er.x : h == 1 ? er.y : h == 2 ? er.z : er.w;
        float x = elh + erh + ee;
        x = x > 0.0f ? x : NEG_SLOPE * x;
        p[h] = __expf(x);
    }
    g_p4[e] = make_float4(p[0], p[1], p[2], p[3]);
}

// ---------------- scan kernels (exclusive prefix sum over g_cnt) --------------
__global__ void k_scan1(int N) {
    __shared__ int sh[SCAN_B];
    int t = threadIdx.x;
    int g = blockIdx.x * SCAN_B + t;
    int v = (g < N) ? g_cnt[g] : 0;
    sh[t] = v;
    __syncthreads();
    #pragma unroll
    for (int off = 1; off < SCAN_B; off <<= 1) {
        int x = (t >= off) ? sh[t - off] : 0;
        __syncthreads();
        sh[t] += x;
        __syncthreads();
    }
    if (g < N) g_off[g] = sh[t] - v;            // exclusive
    if (t == SCAN_B - 1) g_bsum[blockIdx.x] = sh[t];
}
__global__ void k_scan2(int NB) {
    __shared__ int sh[128];
    int t = threadIdx.x;
    int v = (t < NB) ? g_bsum[t] : 0;
    sh[t] = v;
    __syncthreads();
    #pragma unroll
    for (int off = 1; off < 128; off <<= 1) {
        int x = (t >= off) ? sh[t - off] : 0;
        __syncthreads();
        sh[t] += x;
        __syncthreads();
    }
    if (t < NB) g_boff[t] = sh[t] - v;
}
__global__ void k_scan3(int N) {
    int g = blockIdx.x * blockDim.x + threadIdx.x;
    if (g < N) {
        int o = g_off[g] + g_boff[g / SCAN_B];
        g_off[g] = o;
        g_cur[g] = o;
    }
}

// ---------------- kernel: bucket {eid,src} by dst ------------------------------
// Also carries src so passC never does the dependent eid->src gather.
__global__ void k_scatteridx(const int* __restrict__ src,
                             const int* __restrict__ dst, int E) {
    int e = blockIdx.x * blockDim.x + threadIdx.x;
    if (e >= E) return;
    int d = __ldg(&dst[e]);
    int s = __ldg(&src[e]);
    int pos = atomicAdd(&g_cur[d], 1);
    g_es[pos] = make_int2(e, s);
}

// ---------------- kernel: CSR aggregation, one warp per dst node --------------
// Batch-loads 32 {eid,src} pairs coalesced, broadcasts via shfl, so the inner
// loop's featp/p4 loads are mutually independent (high MLP). No atomics.
// NOTE: no min-blocks occupancy cap — R6's __launch_bounds__(256,6) forced
// regs<=42 and spilled the inner loop to local memory (the 300us pathology).
__global__ void __launch_bounds__(256)
k_passC(const float* __restrict__ edge_fea, int N) {
    int warp = (blockIdx.x * blockDim.x + threadIdx.x) >> 5;
    int lane = threadIdx.x & 31;
    if (warp >= N) return;
    int off = g_off[warp];
    int deg = g_cnt[warp];

    int h2 = lane / 6, c = lane % 6;          // z/s mapping (lane<24)
    bool zs = lane < 24;
    int psel = lane >> 4;                      // selects head within pair

    float a0 = 0.0f, a1 = 0.0f, a2 = 0.0f;
    for (int base = 0; base < deg; base += 32) {
        int rem = deg - base;
        int cnt = rem < 32 ? rem : 32;
        // coalesced batch load of {eid, src} (one pair per lane)
        int2 es = (lane < cnt) ? __ldg(&g_es[off + base + lane]) : make_int2(0, 0);
        #pragma unroll 4
        for (int i = 0; i < cnt; i++) {
            int eid = __shfl_sync(0xffffffffu, es.x, i);
            int s   = __shfl_sync(0xffffffffu, es.y, i);
            float4 p4 = g_p4[eid];
            float pf0 = psel ? p4.y : p4.x;    // heads 0/1, channels 0..31
            float pf1 = psel ? p4.w : p4.z;    // heads 2/3, channels 32..63
            float v0 = __ldg(&g_featp[s * 64 + lane]);
            float v1 = __ldg(&g_featp[s * 64 + 32 + lane]);
            a0 += pf0 * v0;
            a1 += pf1 * v1;
            if (zs) {
                float ph = h2 == 0 ? p4.x : h2 == 1 ? p4.y : h2 == 2 ? p4.z : p4.w;
                float w = (c == 0) ? 1.0f : __ldg(&edge_fea[eid * ED + (c - 1)]);
                a2 += ph * w;
            }
        }
    }
    g_ft[warp * 64 + lane]      = a0;
    g_ft[warp * 64 + 32 + lane] = a1;
    if (zs) g_zs[(warp * H + h2) * 8 + c] = a2;
}

// ---------------- kernel: normalize + W_edg fold + output GEMV ----------------
__global__ void k_output(const float* __restrict__ W_edg,
                         const float* __restrict__ b_edg,
                         const float* __restrict__ W_out,
                         const float* __restrict__ b_out,
                         const float* __restrict__ bias,
                         float* __restrict__ out, int N) {
    __shared__ float sWo[(ED + D) * D];
    __shared__ float sWe[ED * H * ED];
    __shared__ float sbe[H * ED];
    __shared__ float sb[D];
    __shared__ float sbias[H * D];
    int tid = threadIdx.x;
    for (int i = tid; i < (ED + D) * D; i += 256) sWo[i] = W_out[i];
    if (tid < 100) sWe[tid] = W_edg[tid];
    if (tid < 20)  sbe[tid] = b_edg[tid];
    if (tid < D)   sb[tid] = b_out[tid];
    if (tid < H * D) sbias[tid] = bias[tid];
    __syncthreads();

    int nh = blockIdx.x * blockDim.x + tid;
    if (nh >= N * H) return;
    int n = nh >> 2, h = nh & 3;

    const float4* z4 = (const float4*)&g_zs[nh * 8];
    float4 a0 = z4[0], a1 = z4[1];
    float z = a0.x;
    float inv = z > 0.0f ? 1.0f / z : 0.0f;
    float s0 = a0.y, s1 = a0.z, s2 = a0.w, s3 = a1.x, s4 = a1.y;

    const float4* f4 = (const float4*)&g_ft[n * 64 + h * D];
    float4 b0 = f4[0], b1 = f4[1], b2 = f4[2], b3 = f4[3];
    float ft[D] = {b0.x, b0.y, b0.z, b0.w, b1.x, b1.y, b1.z, b1.w,
                   b2.x, b2.y, b2.z, b2.w, b3.x, b3.y, b3.z, b3.w};

    float ep[ED];
    #pragma unroll
    for (int k = 0; k < ED; k++) {
        float v = z * sbe[h * ED + k];
        v += s0 * sWe[0 * (H * ED) + h * ED + k];
        v += s1 * sWe[1 * (H * ED) + h * ED + k];
        v += s2 * sWe[2 * (H * ED) + h * ED + k];
        v += s3 * sWe[3 * (H * ED) + h * ED + k];
        v += s4 * sWe[4 * (H * ED) + h * ED + k];
        ep[k] = v * inv;
    }
    #pragma unroll
    for (int k = 0; k < D; k++) ft[k] *= inv;

    float o[D];
    #pragma unroll
    for (int dd = 0; dd < D; dd++) o[dd] = sb[dd] + sbias[h * D + dd];
    #pragma unroll
    for (int k = 0; k < ED; k++)
        #pragma unroll
        for (int dd = 0; dd < D; dd++) o[dd] += ep[k] * sWo[k * D + dd];
    #pragma unroll
    for (int k = 0; k < D; k++)
        #pragma unroll
        for (int dd = 0; dd < D; dd++) o[dd] += ft[k] * sWo[(ED + k) * D + dd];

    float4* op = (float4*)&out[nh * D];
    op[0] = make_float4(o[0],  o[1],  o[2],  o[3]);
    op[1] = make_float4(o[4],  o[5],  o[6],  o[7]);
    op[2] = make_float4(o[8],  o[9],  o[10], o[11]);
    op[3] = make_float4(o[12], o[13], o[14], o[15]);
}

// ---------------- launch ------------------------------------------------------
extern "C" void kernel_launch(void* const* d_in, const int* in_sizes, int n_in,
                              void* d_out, int out_size) {
    const float* feat     = (const float*)d_in[0];
    const float* edge_fea = (const float*)d_in[1];
    const int*   src      = (const int*)  d_in[2];
    const int*   dst      = (const int*)  d_in[3];
    const float* W_fc     = (const float*)d_in[4];
    const float* W_edg    = (const float*)d_in[5];
    const float* b_edg    = (const float*)d_in[6];
    const float* attn_l   = (const float*)d_in[7];
    const float* attn_r   = (const float*)d_in[8];
    const float* attn_edg = (const float*)d_in[9];
    const float* W_out    = (const float*)d_in[10];
    const float* b_out    = (const float*)d_in[11];
    const float* bias     = (const float*)d_in[12];
    float* out = (float*)d_out;

    int N = in_sizes[0] / FI;
    int E = in_sizes[2];
    if (N > MAXN) N = MAXN;
    if (E > MAXE) E = MAXE;
    int NB = (N + SCAN_B - 1) / SCAN_B;

    k_zero<<<(N + 255) / 256, 256>>>(N);
    k_nodeproj<<<(N + NPB - 1) / NPB, 256>>>(feat, W_fc, attn_l, attn_r, N);
    k_passB<<<(E + 255) / 256, 256>>>(edge_fea, src, dst, W_edg, b_edg, attn_edg, E);
    k_scan1<<<NB, SCAN_B>>>(N);
    k_scan2<<<1, 128>>>(NB);
    k_scan3<<<(N + 255) / 256, 256>>>(N);
    k_scatteridx<<<(E + 255) / 256, 256>>>(src, dst, E);
    k_passC<<<(N * 32 + 255) / 256, 256>>>(edge_fea, N);
    k_output<<<(N * H + 255) / 256, 256>>>(W_edg, b_edg, W_out, b_out, bias, out, N);
}

// round 11
// speedup vs baseline: 1.3959x; 1.1871x over previous
#include <cuda_runtime.h>
#include <cuda_bf16.h>
#include <cstdint>

#define MAXN 100000
#define MAXE 1600000
#define FI   64
#define H    4
#define D    16
#define ED   5
#define NEG_SLOPE 0.2f
#define NPB   32   // nodes per block in k_nodeproj

// ---------------- static device scratch --------------------------------------
__device__ float  g_featp[MAXN * FI];     // [N,64] projected feats (h*16+d)
__device__ float4 g_el[MAXN];             // [N,4]
__device__ float4 g_er[MAXN];             // [N,4]
// unified accumulator: per (n,h) a 24-float row: {z, s0..s4, pad, pad, ft0..ft15}
__device__ float4 g_acc[MAXN * H * 6];

// sm_90+ vector reductions resolved at L2
__device__ __forceinline__ void red_add4(float* p, float a, float b, float c, float d) {
    unsigned long long g = (unsigned long long)__cvta_generic_to_global(p);
    asm volatile("red.global.add.v4.f32 [%0], {%1, %2, %3, %4};"
                 :: "l"(g), "f"(a), "f"(b), "f"(c), "f"(d) : "memory");
}
__device__ __forceinline__ void red_add2(float* p, float a, float b) {
    unsigned long long g = (unsigned long long)__cvta_generic_to_global(p);
    asm volatile("red.global.add.v2.f32 [%0], {%1, %2};"
                 :: "l"(g), "f"(a), "f"(b) : "memory");
}

// ---------------- kernel 1: zero accumulators ---------------------------------
__global__ void k_init(int N) {
    int t = blockIdx.x * blockDim.x + threadIdx.x;
    if (t < N * H * 6) g_acc[t] = make_float4(0.f, 0.f, 0.f, 0.f);
}

// ---------------- kernel 2: node projection + el/er ---------------------------
// 32 nodes/block: W_fc (16KB) loaded into smem once per block.
__global__ void k_nodeproj(const float* __restrict__ feat,
                           const float* __restrict__ W_fc,
                           const float* __restrict__ attn_l,
                           const float* __restrict__ attn_r, int N) {
    __shared__ float sW[FI * 64];
    __shared__ float sf[4][FI];
    int tid = threadIdx.x;
    #pragma unroll
    for (int i = tid; i < FI * 64; i += 256) sW[i] = W_fc[i];
    int nl = tid >> 6, j = tid & 63;
    int h = j >> 4, d = j & 15;
    float al = __ldg(&attn_l[h * D + d]);
    float ar = __ldg(&attn_r[h * D + d]);

    #pragma unroll
    for (int it = 0; it < NPB / 4; it++) {
        int n = blockIdx.x * NPB + it * 4 + nl;
        __syncthreads();                       // sW ready (it=0) / sf reuse safe
        if (n < N) sf[nl][j] = feat[n * FI + j];
        __syncthreads();
        if (n >= N) continue;

        float acc = 0.0f;
        #pragma unroll
        for (int i = 0; i < FI; i++) acc += sf[nl][i] * sW[i * 64 + j];
        g_featp[n * 64 + j] = acc;

        float elp = acc * al;
        float erp = acc * ar;
        #pragma unroll
        for (int off = 8; off; off >>= 1) {
            elp += __shfl_xor_sync(0xffffffffu, elp, off);
            erp += __shfl_xor_sync(0xffffffffu, erp, off);
        }
        if (d == 0) {
            ((float*)g_el)[n * 4 + h] = elp;
            ((float*)g_er)[n * 4 + h] = erp;
        }
    }
}

// ---------------- kernel 3: FUSED edge pass (measured-good R3 version) --------
// 4 threads/edge (one per head). Folded logit: ee = ef . w_h + c_h.
// Scatters {p, p*ef} (v4+v2) and p*featp[src] (4x v4), unnormalized.
__global__ void k_edge(const float* __restrict__ edge_fea,
                       const int* __restrict__ src,
                       const int* __restrict__ dst,
                       const float* __restrict__ W_edg,
                       const float* __restrict__ b_edg,
                       const float* __restrict__ attn_edg, int E) {
    __shared__ float sw[H][ED];
    __shared__ float sc[H];
    int tid = threadIdx.x;
    if (tid < H * ED) {
        int h = tid / ED, j = tid % ED;
        float a = 0.0f;
        #pragma unroll
        for (int k = 0; k < ED; k++)
            a += W_edg[j * (H * ED) + h * ED + k] * attn_edg[h * ED + k];
        sw[h][j] = a;
    }
    if (tid < H) {
        float a = 0.0f;
        #pragma unroll
        for (int k = 0; k < ED; k++) a += b_edg[tid * ED + k] * attn_edg[tid * ED + k];
        sc[tid] = a;
    }
    __syncthreads();

    int gt = blockIdx.x * blockDim.x + tid;
    int e = gt >> 2, h = gt & 3;
    if (e >= E) return;
    int s = __ldg(&src[e]), d = __ldg(&dst[e]);

    float ef[ED];
    #pragma unroll
    for (int j = 0; j < ED; j++) ef[j] = __ldg(&edge_fea[e * ED + j]);

    float ee = sc[h];
    #pragma unroll
    for (int j = 0; j < ED; j++) ee += ef[j] * sw[h][j];

    float x = ((const float*)g_el)[s * 4 + h] + ((const float*)g_er)[d * 4 + h] + ee;
    x = x > 0.0f ? x : NEG_SLOPE * x;
    float p = __expf(x);

    float* row = (float*)&g_acc[(d * H + h) * 6];
    red_add4(row,     p,         p * ef[0], p * ef[1], p * ef[2]);
    red_add2(row + 4, p * ef[3], p * ef[4]);

    const float4* fp = (const float4*)&g_featp[s * 64 + h * D];
    #pragma unroll
    for (int i = 0; i < 4; i++) {
        float4 v = __ldg(&fp[i]);
        red_add4(row + 8 + 4 * i, p * v.x, p * v.y, p * v.z, p * v.w);
    }
}

// ---------------- kernel 4: normalize + W_edg fold + output GEMV --------------
// smem-stages 256 accumulator rows with coalesced loads (fixes the 6x L1
// wavefront inflation seen at 25.5us / L1=61.6% in R3's profile).
__global__ void k_output(const float* __restrict__ W_edg,
                         const float* __restrict__ b_edg,
                         const float* __restrict__ W_out,
                         const float* __restrict__ b_out,
                         const float* __restrict__ bias,
                         float* __restrict__ out, int N) {
    __shared__ float sWo[(ED + D) * D];
    __shared__ float sWe[ED * H * ED];
    __shared__ float sbe[H * ED];
    __shared__ float sb[D];
    __shared__ float sbias[H * D];
    __shared__ float sF[256 * 25];        // 256 rows x 24 floats, stride 25 (25.6KB)
    int tid = threadIdx.x;
    for (int i = tid; i < (ED + D) * D; i += 256) sWo[i] = W_out[i];
    if (tid < 100) sWe[tid] = W_edg[tid];
    if (tid < 20)  sbe[tid] = b_edg[tid];
    if (tid < D)   sb[tid] = b_out[tid];
    if (tid < H * D) sbias[tid] = bias[tid];

    int base = blockIdx.x * 256;          // first nh row of this block
    int rows = N * H - base;
    if (rows > 256) rows = 256;
    const float* gacc = (const float*)g_acc;
    for (int i = tid; i < rows * 24; i += 256) {
        int r = i / 24, c = i - r * 24;
        sF[r * 25 + c] = gacc[base * 24 + i];
    }
    __syncthreads();

    int nh = base + tid;
    if (nh >= N * H) return;
    int h = nh & 3;

    const float* row = &sF[tid * 25];
    float z = row[0];
    float inv = z > 0.0f ? 1.0f / z : 0.0f;
    float s0 = row[1], s1 = row[2], s2 = row[3], s3 = row[4], s4 = row[5];

    float ft[D];
    #pragma unroll
    for (int k = 0; k < D; k++) ft[k] = row[8 + k] * inv;

    float ep[ED];
    #pragma unroll
    for (int k = 0; k < ED; k++) {
        float v = z * sbe[h * ED + k];
        v += s0 * sWe[0 * (H * ED) + h * ED + k];
        v += s1 * sWe[1 * (H * ED) + h * ED + k];
        v += s2 * sWe[2 * (H * ED) + h * ED + k];
        v += s3 * sWe[3 * (H * ED) + h * ED + k];
        v += s4 * sWe[4 * (H * ED) + h * ED + k];
        ep[k] = v * inv;
    }

    float o[D];
    #pragma unroll
    for (int dd = 0; dd < D; dd++) o[dd] = sb[dd] + sbias[h * D + dd];
    #pragma unroll
    for (int k = 0; k < ED; k++)
        #pragma unroll
        for (int dd = 0; dd < D; dd++) o[dd] += ep[k] * sWo[k * D + dd];
    #pragma unroll
    for (int k = 0; k < D; k++)
        #pragma unroll
        for (int dd = 0; dd < D; dd++) o[dd] += ft[k] * sWo[(ED + k) * D + dd];

    float4* op = (float4*)&out[nh * D];
    op[0] = make_float4(o[0],  o[1],  o[2],  o[3]);
    op[1] = make_float4(o[4],  o[5],  o[6],  o[7]);
    op[2] = make_float4(o[8],  o[9],  o[10], o[11]);
    op[3] = make_float4(o[12], o[13], o[14], o[15]);
}

// ---------------- launch ------------------------------------------------------
extern "C" void kernel_launch(void* const* d_in, const int* in_sizes, int n_in,
                              void* d_out, int out_size) {
    const float* feat     = (const float*)d_in[0];
    const float* edge_fea = (const float*)d_in[1];
    const int*   src      = (const int*)  d_in[2];
    const int*   dst      = (const int*)  d_in[3];
    const float* W_fc     = (const float*)d_in[4];
    const float* W_edg    = (const float*)d_in[5];
    const float* b_edg    = (const float*)d_in[6];
    const float* attn_l   = (const float*)d_in[7];
    const float* attn_r   = (const float*)d_in[8];
    const float* attn_edg = (const float*)d_in[9];
    const float* W_out    = (const float*)d_in[10];
    const float* b_out    = (const float*)d_in[11];
    const float* bias     = (const float*)d_in[12];
    float* out = (float*)d_out;

    int N = in_sizes[0] / FI;
    int E = in_sizes[2];
    if (N > MAXN) N = MAXN;
    if (E > MAXE) E = MAXE;

    k_init<<<(N * H * 6 + 255) / 256, 256>>>(N);
    k_nodeproj<<<(N + NPB - 1) / NPB, 256>>>(feat, W_fc, attn_l, attn_r, N);
    k_edge<<<(E * 4 + 255) / 256, 256>>>(edge_fea, src, dst, W_edg, b_edg, attn_edg, E);
    k_output<<<(N * H + 255) / 256, 256>>>(W_edg, b_edg, W_out, b_out, bias, out, N);
}